// round 2
// baseline (speedup 1.0000x reference)
#include <cuda_runtime.h>
#include <cstdint>
#include <cstddef>

#define NB   128      // batches
#define NT   2048     // tokens per batch
#define NH   64       // hidden / features
#define NS   64       // segments

// ---------------- scratch (device globals: allocation-free) ----------------
__device__ float d_hA[(size_t)NB * NH * NT];   // hT of layer0 output: [b][f][n]
__device__ float d_hB[(size_t)NB * NH * NT];   // hT of layer1 output: [b][f][n]
__device__ float d_G [(size_t)NB * NS * NH];   // G[b][seg][f] = agg @ W_next_bottom
__device__ float d_agg[(size_t)NB * NS * NH];  // final layer-2 agg: [b][seg][f]
__device__ unsigned char d_cl[(size_t)NB * NT];
__device__ int d_is32;

typedef unsigned long long u64;

__device__ __forceinline__ u64 pack2(float lo, float hi) {
    u64 r; asm("mov.b64 %0, {%1, %2};" : "=l"(r) : "f"(lo), "f"(hi)); return r;
}
__device__ __forceinline__ void unpack2(u64 v, float& lo, float& hi) {
    asm("mov.b64 {%0, %1}, %2;" : "=f"(lo), "=f"(hi) : "l"(v));
}
__device__ __forceinline__ u64 fma2(u64 a, u64 b, u64 c) {
    u64 d; asm("fma.rn.f32x2 %0, %1, %2, %3;" : "=l"(d) : "l"(a), "l"(b), "l"(c)); return d;
}
__device__ __forceinline__ u64 add2(u64 a, u64 b) {
    u64 d; asm("add.rn.f32x2 %0, %1, %2;" : "=l"(d) : "l"(a), "l"(b)); return d;
}

// ---------------- cluster dtype sniff + convert ----------------
// jnp.int64 may silently be int32 if x64 is disabled. Distinguish: viewed as
// int32 words, an int64 buffer of values in [0,64) has ALL odd words == 0.
__global__ void k_init() { d_is32 = 0; }

__global__ void k_scan(const int* __restrict__ cl) {
    int i = blockIdx.x * blockDim.x + threadIdx.x;   // 131072 threads
    int idx = 2 * i + 1;
    if (idx < NB * NT) {
        if (cl[idx] != 0) d_is32 = 1;   // racy same-value store: deterministic
    }
}

__global__ void k_conv(const int* __restrict__ cl32, const long long* __restrict__ cl64) {
    int n = blockIdx.x * blockDim.x + threadIdx.x;
    if (n < NB * NT) {
        if (d_is32) d_cl[n] = (unsigned char)cl32[n];
        else        d_cl[n] = (unsigned char)(int)cl64[n];
    }
}

// ---------------- fused layer kernel ----------------
// LAYER 0: in = x [B][N][8], K=8, no G-gather, writes d_hA, makes G (Wnb=W1_bot)
// LAYER 1: in = d_hA [b][f][n], K=64, gathers d_G, writes d_hB, makes G (Wnb=W2_bot)
// LAYER 2: in = d_hB, K=64, gathers d_G, writes d_agg only (h2 never materialized)
template <int LAYER>
__global__ __launch_bounds__(512, 1)
void k_layer(const float* __restrict__ x,
             const float* __restrict__ Wtop,   // [CIN][64] row-major (k-major)
             const float* __restrict__ bias,
             const float* __restrict__ gam,
             const float* __restrict__ bet,
             const float* __restrict__ Wnb)    // next layer's W[64:128][:] (unused layer 2)
{
    constexpr int  CIN     = (LAYER == 0) ? 8 : 64;
    constexpr bool HAS_G   = (LAYER != 0);
    constexpr bool WRITE_H = (LAYER != 2);
    constexpr bool MAKE_G  = (LAYER != 2);
    constexpr bool WRITE_A = (LAYER == 2);

    __shared__ __align__(16) float    sW [CIN * NH];                  // 2KB or 16KB
    __shared__ __align__(16) float    sBG[HAS_G ? (NS * NH) : NH];    // bias (+G), swizzled
    __shared__               unsigned sAgg[NS * NH];                  // bit-max, swizzled

    const int b   = blockIdx.x;
    const int tid = threadIdx.x;

    for (int i = tid; i < CIN * NH; i += 512) sW[i] = Wtop[i];
    for (int i = tid; i < NS * NH; i += 512) sAgg[i] = 0u;
    if (HAS_G) {
        const float* gin = d_G + (size_t)b * NS * NH;
        for (int i = tid; i < NS * NH; i += 512) {
            int seg = i >> 6, f = i & 63;
            // swizzle by 4*seg: keeps 16B vector alignment, spreads banks
            sBG[seg * 64 + ((f + 4 * seg) & 63)] = bias[f] + gin[i];
        }
    } else {
        if (tid < NH) sBG[tid] = bias[tid];
    }
    __syncthreads();

    const int warp = tid >> 5, lane = tid & 31;
    const float* inp = (LAYER == 0) ? x : ((LAYER == 1) ? d_hA : d_hB);
    float* hOut = (LAYER == 0) ? d_hA : d_hB;

    for (int t = 0; t < NT / 512; t++) {
        const int token = warp * 128 + t * 32 + lane;
        const int seg   = d_cl[b * NT + token];

        u64 a[32];
        if (HAS_G) {
            const int sb = seg * 64, sh = (seg * 4) & 63;
            #pragma unroll
            for (int j = 0; j < 16; j++) {
                ulonglong2 v = *(const ulonglong2*)&sBG[sb + ((j * 4 + sh) & 63)];
                a[2 * j] = v.x; a[2 * j + 1] = v.y;
            }
        } else {
            #pragma unroll
            for (int j = 0; j < 16; j++) {
                ulonglong2 v = *(const ulonglong2*)&sBG[j * 4];
                a[2 * j] = v.x; a[2 * j + 1] = v.y;
            }
        }

        if (LAYER == 0) {
            const float4* xp = (const float4*)(x + ((size_t)b * NT + token) * 8);
            float4 x0 = __ldg(xp), x1 = __ldg(xp + 1);
            float xv[8] = {x0.x, x0.y, x0.z, x0.w, x1.x, x1.y, x1.z, x1.w};
            #pragma unroll
            for (int k = 0; k < 8; k++) {
                u64 hk = pack2(xv[k], xv[k]);
                const ulonglong2* wr = (const ulonglong2*)&sW[k * 64];
                #pragma unroll
                for (int j = 0; j < 16; j++) {
                    ulonglong2 w = wr[j];
                    a[2 * j]     = fma2(hk, w.x, a[2 * j]);
                    a[2 * j + 1] = fma2(hk, w.y, a[2 * j + 1]);
                }
            }
        } else {
            const float* ip = inp + (size_t)b * NH * NT + token;
            #pragma unroll 8
            for (int k = 0; k < 64; k++) {
                float hv = __ldg(ip + (size_t)k * NT);
                u64 hk = pack2(hv, hv);
                const ulonglong2* wr = (const ulonglong2*)&sW[k * 64];
                #pragma unroll
                for (int j = 0; j < 16; j++) {
                    ulonglong2 w = wr[j];
                    a[2 * j]     = fma2(hk, w.x, a[2 * j]);
                    a[2 * j + 1] = fma2(hk, w.y, a[2 * j + 1]);
                }
            }
        }

        // ---- LayerNorm + affine + ReLU (all 64 values live in this lane) ----
        u64 s = a[0];
        #pragma unroll
        for (int j = 1; j < 32; j++) s = add2(s, a[j]);
        float se, so; unpack2(s, se, so);
        const float mu = (se + so) * (1.0f / 64.0f);
        const u64 nmu = pack2(-mu, -mu);
        u64 q = 0;
        #pragma unroll
        for (int j = 0; j < 32; j++) { u64 dd = add2(a[j], nmu); q = fma2(dd, dd, q); }
        float qe, qo; unpack2(q, qe, qo);
        const float var = (qe + qo) * (1.0f / 64.0f);
        const float rs  = rsqrtf(var + 1e-5f);

        float* ho = hOut + (size_t)b * NH * NT + token;
        #pragma unroll
        for (int j = 0; j < 32; j++) {
            float lo, hi; unpack2(a[j], lo, hi);
            const int f0 = 2 * j;
            float v0 = fmaxf(fmaf((lo - mu) * rs, __ldg(gam + f0),     __ldg(bet + f0)),     0.0f);
            float v1 = fmaxf(fmaf((hi - mu) * rs, __ldg(gam + f0 + 1), __ldg(bet + f0 + 1)), 0.0f);
            if (WRITE_H) {
                ho[(size_t)f0 * NT]       = v0;
                ho[(size_t)(f0 + 1) * NT] = v1;
            }
            // nonneg floats: uint bit-pattern order == float order; init 0 == empty->0
            atomicMax(&sAgg[seg * 64 + ((f0 + seg) & 63)],     __float_as_uint(v0));
            atomicMax(&sAgg[seg * 64 + ((f0 + 1 + seg) & 63)], __float_as_uint(v1));
        }
    }
    __syncthreads();

    if (MAKE_G) {
        // G[b][seg][f] = agg[b][seg][:] @ Wnb   (64x64x64, trivial)
        const int seg = tid >> 3;
        const int f0  = (tid & 7) * 8;
        float acc[8];
        #pragma unroll
        for (int u = 0; u < 8; u++) acc[u] = 0.0f;
        #pragma unroll 8
        for (int k = 0; k < 64; k++) {
            float av = __uint_as_float(sAgg[seg * 64 + ((k + seg) & 63)]);
            const float4* wp = (const float4*)(Wnb + k * 64 + f0);
            float4 wa = __ldg(wp), wb = __ldg(wp + 1);
            acc[0] += av * wa.x; acc[1] += av * wa.y; acc[2] += av * wa.z; acc[3] += av * wa.w;
            acc[4] += av * wb.x; acc[5] += av * wb.y; acc[6] += av * wb.z; acc[7] += av * wb.w;
        }
        float* gp = d_G + ((size_t)b * NS + seg) * NH + f0;
        #pragma unroll
        for (int u = 0; u < 8; u++) gp[u] = acc[u];
    }

    if (WRITE_A) {
        for (int i = tid; i < NS * NH; i += 512) {
            int seg = i >> 6, f = i & 63;
            d_agg[(size_t)b * NS * NH + i] = __uint_as_float(sAgg[seg * 64 + ((f + seg) & 63)]);
        }
    }
}

// ---------------- final: out = tile(agg2, 2) / L2norm-over-segments ----------------
__global__ void k_final(float* __restrict__ out) {
    __shared__ float sInv[64];
    const int b = blockIdx.x, tid = threadIdx.x;
    const float* agg = d_agg + (size_t)b * NS * NH;
    if (tid < 64) {
        float ssum = 0.0f;
        const float* p = agg + tid;
        #pragma unroll 8
        for (int c = 0; c < NS; c++) { float v = p[c * NH]; ssum = fmaf(v, v, ssum); }
        float nrm = sqrtf(ssum);
        sInv[tid] = 1.0f / fmaxf(nrm, 1e-12f);
    }
    __syncthreads();
    for (int i = tid; i < NS * 128; i += blockDim.x) {
        int c = i >> 7, f = i & 127, f6 = f & 63;
        out[(size_t)b * NS * 128 + i] = agg[c * NH + f6] * sInv[f6];
    }
}

// ---------------- launch ----------------
extern "C" void kernel_launch(void* const* d_in, const int* in_sizes, int n_in,
                              void* d_out, int out_size) {
    (void)in_sizes; (void)n_in; (void)out_size;
    const float* x     = (const float*)d_in[0];
    const void*  clraw = d_in[1];
    const float* W0 = (const float*)d_in[2];
    const float* b0 = (const float*)d_in[3];
    const float* g0 = (const float*)d_in[4];
    const float* be0 = (const float*)d_in[5];
    const float* W1 = (const float*)d_in[6];
    const float* b1 = (const float*)d_in[7];
    const float* g1 = (const float*)d_in[8];
    const float* be1 = (const float*)d_in[9];
    const float* W2 = (const float*)d_in[10];
    const float* b2 = (const float*)d_in[11];
    const float* g2 = (const float*)d_in[12];
    const float* be2 = (const float*)d_in[13];
    float* out = (float*)d_out;

    k_init<<<1, 1>>>();
    k_scan<<<512, 256>>>((const int*)clraw);
    k_conv<<<(NB * NT + 511) / 512, 512>>>((const int*)clraw, (const long long*)clraw);

    // W layout: [K][H] row-major. Top = rows 0..63, bottom = rows 64..127.
    k_layer<0><<<NB, 512>>>(x, W0, b0, g0, be0, W1 + 64 * 64);
    k_layer<1><<<NB, 512>>>(x, W1, b1, g1, be1, W2 + 64 * 64);
    k_layer<2><<<NB, 512>>>(x, W2, b2, g2, be2, nullptr);

    k_final<<<NB, 256>>>(out);
}